// round 4
// baseline (speedup 1.0000x reference)
#include <cuda_runtime.h>
#include <cuda_bf16.h>

#define S 1024
#define B 8192
#define EPSF 1e-8f
#define WPB 8
#define THREADS 256
#define LPT 16
#define CHUNK 512
#define NCHUNK 2
#define SPAD (S + S / 32)   // 1056

__device__ __forceinline__ int padi(int i) { return i + (i >> 5); }

__global__ __launch_bounds__(THREADS)
void td_lambda_kernel(const float* __restrict__ raw_gamma,
                      const float* __restrict__ raw_lambd,
                      const float* __restrict__ values,
                      const float* __restrict__ rewards,
                      const int*   __restrict__ dones,
                      float* __restrict__ out)
{
    __shared__ float s_ga[SPAD];          // gamma*lam (padded)
    __shared__ float s_gb[SPAD];          // gamma*(1-lam)
    __shared__ float s_v[WPB][SPAD];      // full-row staged values per warp

    const int tid  = threadIdx.x;
    const int lane = tid & 31;
    const int warp = tid >> 5;
    const float gamma = fmaxf(tanhf(raw_gamma[0]), EPSF);

    for (int i = tid; i < S; i += THREADS) {
        float lam = fmaxf(tanhf(raw_lambd[i]), EPSF);
        s_ga[padi(i)] = gamma * lam;
        s_gb[padi(i)] = gamma * (1.0f - lam);
    }
    __syncthreads();

    if (blockIdx.x < B / WPB) {
        const int b = blockIdx.x * WPB + warp;
        const float* __restrict__ rrow = rewards + (size_t)b * S;
        const int*   __restrict__ drow = dones   + (size_t)b * S;
        const float* __restrict__ vrow = values  + (size_t)b * (S + 1);
        float* __restrict__ orow = out + (size_t)b * S;

        float carry = __ldg(&vrow[S]);

        // ---- prologue: stage ALL values (coalesced), prefetch chunk 1 r/d ----
        float vtmp[32];
        #pragma unroll
        for (int k = 0; k < 32; ++k)
            vtmp[k] = vrow[1 + lane + 32 * k];

        float4 r[4]; int4 d[4];
        {
            const int cb = (NCHUNK - 1) * CHUNK + lane * LPT;
            #pragma unroll
            for (int q = 0; q < 4; ++q) {
                r[q] = *(const float4*)(rrow + cb + 4 * q);
                d[q] = *(const int4*)(drow + cb + 4 * q);
            }
        }
        #pragma unroll
        for (int k = 0; k < 32; ++k)
            s_v[warp][lane + 33 * k] = vtmp[k];   // padi(lane+32k) = lane+33k
        __syncwarp();

        #pragma unroll
        for (int c = NCHUNK - 1; c >= 0; --c) {
            // prefetch next chunk's r/d (hidden behind this chunk's scan)
            float4 nr[4]; int4 nd[4];
            if (c > 0) {
                const int cb = (c - 1) * CHUNK + lane * LPT;
                #pragma unroll
                for (int q = 0; q < 4; ++q) {
                    nr[q] = *(const float4*)(rrow + cb + 4 * q);
                    nd[q] = *(const int4*)(drow + cb + 4 * q);
                }
            }

            const int base = c * CHUNK + lane * LPT;
            // conflict-free padded view: pad(base+j) = base + j + 16c + (lane>>1)
            const float* vbuf = &s_v[warp][base + 16 * c + (lane >> 1)];

            float a[LPT], bb[LPT];
            #pragma unroll
            for (int q = 0; q < 4; ++q) {
                float rr[4] = {r[q].x, r[q].y, r[q].z, r[q].w};
                int   dd[4] = {d[q].x, d[q].y, d[q].z, d[q].w};
                #pragma unroll
                for (int m = 0; m < 4; ++m) {
                    const int j = 4 * q + m;
                    const int t = base + j;
                    float ga = s_ga[padi(t)];
                    float gb = s_gb[padi(t)];
                    float v  = vbuf[j];
                    bool  z  = (dd[m] != 0);
                    a[j]  = z ? 0.0f : ga;
                    bb[j] = z ? rr[m] : fmaf(gb, v, rr[m]);
                }
            }

            // local composition G = F_j0 ∘ ... ∘ F_j15
            float A = a[LPT - 1], Bc = bb[LPT - 1];
            #pragma unroll
            for (int j = LPT - 2; j >= 0; --j) {
                Bc = fmaf(a[j], Bc, bb[j]);
                A  = a[j] * A;
            }

            // warp suffix scan of lane composites
            float sA = A, sB = Bc;
            #pragma unroll
            for (int off = 1; off < 32; off <<= 1) {
                float a2 = __shfl_down_sync(0xffffffffu, sA, off);
                float b2 = __shfl_down_sync(0xffffffffu, sB, off);
                if (lane + off < 32) {
                    sB = fmaf(sA, b2, sB);
                    sA = sA * a2;
                }
            }

            float eA = __shfl_down_sync(0xffffffffu, sA, 1);
            float eB = __shfl_down_sync(0xffffffffu, sB, 1);
            if (lane == 31) { eA = 1.0f; eB = 0.0f; }
            float x = fmaf(eA, carry, eB);

            float cA = __shfl_sync(0xffffffffu, sA, 0);
            float cB = __shfl_sync(0xffffffffu, sB, 0);

            float o[LPT];
            #pragma unroll
            for (int j = LPT - 1; j >= 0; --j) {
                x = fmaf(a[j], x, bb[j]);
                o[j] = x;
            }
            #pragma unroll
            for (int q = 0; q < 4; ++q)
                *(float4*)(orow + base + 4 * q) =
                    make_float4(o[4 * q], o[4 * q + 1], o[4 * q + 2], o[4 * q + 3]);

            carry = fmaf(cA, carry, cB);

            if (c > 0) {
                #pragma unroll
                for (int q = 0; q < 4; ++q) { r[q] = nr[q]; d[q] = nd[q]; }
            }
        }
    } else {
        // ---------------- srw (sum_reward_weights) ----------------
        float* s_w    = &s_v[0][0];     // reuse staging storage
        float* s_part = &s_v[2][0];

        if (tid < 32) {
            float carry = 1.0f;
            for (int c = S / 32 - 1; c >= 0; --c) {
                const int t = c * 32 + lane;
                float a  = s_ga[padi(t)];
                float bb = s_gb[padi(t)];
                #pragma unroll
                for (int off = 1; off < 32; off <<= 1) {
                    float a2 = __shfl_down_sync(0xffffffffu, a,  off);
                    float b2 = __shfl_down_sync(0xffffffffu, bb, off);
                    if (lane + off < 32) {
                        bb = fmaf(a, b2, bb);
                        a  = a * a2;
                    }
                }
                float vv = fmaf(a, carry, bb);
                s_w[t] = fmaxf(1.0f - vv, EPSF);
                carry = __shfl_sync(0xffffffffu, vv, 0);
            }
        }
        __syncthreads();

        float ps = 0.0f;
        for (int i = tid; i < S; i += THREADS) ps += s_w[i];
        s_part[tid] = ps;
        __syncthreads();
        for (int stride = THREADS / 2; stride > 0; stride >>= 1) {
            if (tid < stride) s_part[tid] += s_part[tid + stride];
            __syncthreads();
        }
        float mean = s_part[0] * (1.0f / (float)S);
        float inv  = 1.0f / fmaxf(mean, EPSF);
        for (int i = tid; i < S; i += THREADS)
            out[(size_t)B * S + i] = s_w[i] * inv;
    }
}

extern "C" void kernel_launch(void* const* d_in, const int* in_sizes, int n_in,
                              void* d_out, int out_size) {
    const float* raw_gamma = (const float*)d_in[0];
    const float* raw_lambd = (const float*)d_in[1];
    const float* values    = (const float*)d_in[2];
    const float* rewards   = (const float*)d_in[3];
    const int*   dones     = (const int*)d_in[4];
    float* out = (float*)d_out;

    const int grid = B / WPB + 1;
    td_lambda_kernel<<<grid, THREADS>>>(raw_gamma, raw_lambd, values, rewards, dones, out);
}

// round 5
// speedup vs baseline: 1.0656x; 1.0656x over previous
#include <cuda_runtime.h>
#include <cuda_bf16.h>

#define S 1024
#define B 8192
#define EPSF 1e-8f
#define THREADS 256
#define ROWS_PER_BLOCK 2
#define WARPS_PER_ROW 4
#define SEG 256              // timesteps per warp segment
#define LPT 8                // timesteps per lane
#define NBLK (B / ROWS_PER_BLOCK)   // 4096 row blocks
#define SPAD (S + S / 32)    // 1056

__device__ __forceinline__ int padi(int i) { return i + (i >> 5); }

// Two-level parallel reverse affine scan: 4 warps cooperate on one row.
// Each warp handles one 256-step segment in a single straight-line pass,
// publishes its segment composite, then applies the cross-segment carry.
__global__ __launch_bounds__(THREADS)
void td_lambda_kernel(const float* __restrict__ raw_gamma,
                      const float* __restrict__ raw_lambd,
                      const float* __restrict__ values,
                      const float* __restrict__ rewards,
                      const int*   __restrict__ dones,
                      float* __restrict__ out)
{
    __shared__ float s_ga[SPAD];        // gamma*lam (padded)
    __shared__ float s_gb[SPAD];        // gamma*(1-lam)
    __shared__ float s_v[8][SEG + 8];   // per-warp staged values (padded)
    __shared__ float s_cA[8], s_cB[8];  // per-warp segment composites

    const int tid  = threadIdx.x;
    const int lane = tid & 31;
    const int warp = tid >> 5;
    const float gamma = fmaxf(tanhf(raw_gamma[0]), EPSF);

    for (int i = tid; i < S; i += THREADS) {
        float lam = fmaxf(tanhf(raw_lambd[i]), EPSF);
        s_ga[padi(i)] = gamma * lam;
        s_gb[padi(i)] = gamma * (1.0f - lam);
    }
    __syncthreads();

    if (blockIdx.x < NBLK) {
        const int row_in_blk = warp >> 2;        // 0..1
        const int seg        = warp & 3;         // 0..3
        const int b = blockIdx.x * ROWS_PER_BLOCK + row_in_blk;
        const float* __restrict__ rrow = rewards + (size_t)b * S;
        const int*   __restrict__ drow = dones   + (size_t)b * S;
        const float* __restrict__ vrow = values  + (size_t)b * (S + 1);
        float* __restrict__ orow = out + (size_t)b * S;

        const int segbase = seg * SEG;
        const int base    = segbase + lane * LPT;

        // ---- all loads issued up front (max MLP) ----
        float4 r0 = *(const float4*)(rrow + base);
        float4 r1 = *(const float4*)(rrow + base + 4);
        int4   d0 = *(const int4*)(drow + base);
        int4   d1 = *(const int4*)(drow + base + 4);
        float vtmp[8];
        #pragma unroll
        for (int k = 0; k < 8; ++k)                 // coalesced 32-float runs
            vtmp[k] = vrow[segbase + 1 + lane + 32 * k];
        const float vS = __ldg(&vrow[S]);

        #pragma unroll
        for (int k = 0; k < 8; ++k)                 // padded: bank = lane
            s_v[warp][lane + 33 * k] = vtmp[k];
        __syncwarp();

        // ---- per-step affine coeffs ----
        float r[LPT]  = {r0.x, r0.y, r0.z, r0.w, r1.x, r1.y, r1.z, r1.w};
        int   dn[LPT] = {d0.x, d0.y, d0.z, d0.w, d1.x, d1.y, d1.z, d1.w};
        const float* vbuf = &s_v[warp][lane * LPT + (lane >> 2)];  // conflict-free

        float a[LPT], bb[LPT];
        #pragma unroll
        for (int j = 0; j < LPT; ++j) {
            int t = base + j;
            float ga = s_ga[padi(t)];
            float gb = s_gb[padi(t)];
            float v  = vbuf[j];
            bool  z  = (dn[j] != 0);
            a[j]  = z ? 0.0f : ga;
            bb[j] = z ? r[j] : fmaf(gb, v, r[j]);
        }

        // ---- local composition G = F_j0 ∘ ... ∘ F_j7 ----
        float A = a[LPT - 1], Bc = bb[LPT - 1];
        #pragma unroll
        for (int j = LPT - 2; j >= 0; --j) {
            Bc = fmaf(a[j], Bc, bb[j]);
            A  = a[j] * A;
        }

        // ---- warp suffix scan of lane composites ----
        float sA = A, sB = Bc;
        #pragma unroll
        for (int off = 1; off < 32; off <<= 1) {
            float a2 = __shfl_down_sync(0xffffffffu, sA, off);
            float b2 = __shfl_down_sync(0xffffffffu, sB, off);
            if (lane + off < 32) {
                sB = fmaf(sA, b2, sB);
                sA = sA * a2;
            }
        }

        // publish segment composite (lane 0 holds full-segment map)
        if (lane == 0) { s_cA[warp] = sA; s_cB[warp] = sB; }
        __syncthreads();

        // ---- entry carry: apply segments seg+1..3 to v_S (≤3 FMAs) ----
        float carry = vS;
        #pragma unroll
        for (int k = 3; k >= 1; --k) {
            if (k > seg) {
                int w = (row_in_blk << 2) | k;
                carry = fmaf(s_cA[w], carry, s_cB[w]);
            }
        }

        // per-lane entry value from warp suffix at lane+1
        float eA = __shfl_down_sync(0xffffffffu, sA, 1);
        float eB = __shfl_down_sync(0xffffffffu, sB, 1);
        if (lane == 31) { eA = 1.0f; eB = 0.0f; }
        float x = fmaf(eA, carry, eB);

        // ---- replay 8 outputs ----
        float o[LPT];
        #pragma unroll
        for (int j = LPT - 1; j >= 0; --j) {
            x = fmaf(a[j], x, bb[j]);
            o[j] = x;
        }
        *(float4*)(orow + base)     = make_float4(o[0], o[1], o[2], o[3]);
        *(float4*)(orow + base + 4) = make_float4(o[4], o[5], o[6], o[7]);
    } else {
        // ---------------- srw (sum_reward_weights) ----------------
        float* s_w    = &s_v[0][0];   // reuse staging (2112 floats available)
        float* s_part = &s_v[4][0];

        if (tid < 32) {
            float carry = 1.0f;
            for (int c = S / 32 - 1; c >= 0; --c) {
                const int t = c * 32 + lane;
                float a  = s_ga[padi(t)];
                float bb = s_gb[padi(t)];
                #pragma unroll
                for (int off = 1; off < 32; off <<= 1) {
                    float a2 = __shfl_down_sync(0xffffffffu, a,  off);
                    float b2 = __shfl_down_sync(0xffffffffu, bb, off);
                    if (lane + off < 32) {
                        bb = fmaf(a, b2, bb);
                        a  = a * a2;
                    }
                }
                float vv = fmaf(a, carry, bb);
                s_w[t] = fmaxf(1.0f - vv, EPSF);
                carry = __shfl_sync(0xffffffffu, vv, 0);
            }
        }
        __syncthreads();

        float ps = 0.0f;
        for (int i = tid; i < S; i += THREADS) ps += s_w[i];
        s_part[tid] = ps;
        __syncthreads();
        for (int stride = THREADS / 2; stride > 0; stride >>= 1) {
            if (tid < stride) s_part[tid] += s_part[tid + stride];
            __syncthreads();
        }
        float mean = s_part[0] * (1.0f / (float)S);
        float inv  = 1.0f / fmaxf(mean, EPSF);
        for (int i = tid; i < S; i += THREADS)
            out[(size_t)B * S + i] = s_w[i] * inv;
    }
}

extern "C" void kernel_launch(void* const* d_in, const int* in_sizes, int n_in,
                              void* d_out, int out_size) {
    const float* raw_gamma = (const float*)d_in[0];
    const float* raw_lambd = (const float*)d_in[1];
    const float* values    = (const float*)d_in[2];
    const float* rewards   = (const float*)d_in[3];
    const int*   dones     = (const int*)d_in[4];
    float* out = (float*)d_out;

    td_lambda_kernel<<<NBLK + 1, THREADS>>>(raw_gamma, raw_lambd, values, rewards, dones, out);
}